// round 3
// baseline (speedup 1.0000x reference)
#include <cuda_runtime.h>
#include <math.h>

// Problem constants
#define VV   32000
#define EE   256
#define DDIM 25
#define BB   64
#define TTOT 24
#define HH   625      // D*D
// xs layout per batch row: [0,25) cU | [25,281) word | [281,906) cS | [906,1531) hS | [1531,1556) hU | pad -> 1568
#define KP   1568     // padded K for gate GEMM (49*32)
#define NR   2624     // padded gate rows (41*64); real gates = 2600
#define KSPLIT 7
#define KSEG   224    // KP / KSPLIT, = 7 chunks of 32
#define WO_LD  640    // padded H for FC GEMM

// Scratch (device globals; no allocation at runtime)
__device__ float d_Wcat[NR * KP];          // 16.5 MB
__device__ float d_bias[NR];
__device__ float d_fcWp[VV * WO_LD];       // 81.9 MB padded fcW
__device__ float d_xs[BB * KP];            // state vector per batch
__device__ float d_gpart[KSPLIT * BB * NR];// split-K partials
__device__ float d_wordOut[TTOT * BB * WO_LD]; // FC input, slice0 = zeros

__device__ __forceinline__ float sigm(float x) { return 1.0f / (1.0f + expf(-x)); }

// ---------------------------------------------------------------------------
// Prep: build concatenated gate weight matrix + summed bias (runs every launch,
// deterministic). Rows 0..2499: lstmS gates (i,f,g,o x 625). Rows 2500..2599:
// lstmU gates (i,f,g,o x 25). Rows 2600..2623 zero padding.
// Columns: [0,906) Wih (acts on cU|word|cS), [906,1531) WhhS (acts on hS),
// [1531,1556) WhhU (acts on hU), rest zero.
// ---------------------------------------------------------------------------
__global__ void k_prep_wcat(const float* __restrict__ WihS, const float* __restrict__ WhhS,
                            const float* __restrict__ bihS, const float* __restrict__ bhhS,
                            const float* __restrict__ WihU, const float* __restrict__ WhhU,
                            const float* __restrict__ bihU, const float* __restrict__ bhhU) {
    int r = blockIdx.x;
    int tid = threadIdx.x;
    for (int c = tid; c < KP; c += 256) {
        float v = 0.0f;
        if (r < 2500) {
            if (c < 906)        v = WihS[r * 906 + c];
            else if (c < 1531)  v = WhhS[r * 625 + (c - 906)];
        } else if (r < 2600) {
            int r2 = r - 2500;
            if (c < 906)                   v = WihU[r2 * 906 + c];
            else if (c >= 1531 && c < 1556) v = WhhU[r2 * 25 + (c - 1531)];
        }
        d_Wcat[r * KP + c] = v;
    }
    if (tid == 0) {
        float bv = 0.0f;
        if (r < 2500)       bv = bihS[r] + bhhS[r];
        else if (r < 2600)  bv = bihU[r - 2500] + bhhU[r - 2500];
        d_bias[r] = bv;
    }
}

// Pad fcW [32000 x 625] -> [32000 x 640] (zeros in pad cols)
__global__ void k_prep_fcw(const float* __restrict__ fcW) {
    int n = blockIdx.x;
    int tid = threadIdx.x;
    for (int k = tid; k < WO_LD; k += 256)
        d_fcWp[n * WO_LD + k] = (k < 625) ? fcW[n * 625 + k] : 0.0f;
}

// Zero wordOut (slice 0 must be zeros; pad columns must be zeros)
__global__ void k_zero_wo() {
    int i = blockIdx.x * 256 + threadIdx.x;
    if (i < TTOT * BB * WO_LD) d_wordOut[i] = 0.0f;
}

// Init state: xs = [cU=0 | word0=embed[0] | cS=sStart | hS=0 | hU=0 | pad=0]
// sStart = features @ szW.T + szb
__global__ void k_init(const float* __restrict__ features, const float* __restrict__ szW,
                       const float* __restrict__ szb, const float* __restrict__ embed) {
    int b = blockIdx.x;
    int tid = threadIdx.x;
    __shared__ float sf[EE];
    for (int k = tid; k < KP; k += 256) d_xs[b * KP + k] = 0.0f;
    for (int e = tid; e < EE; e += 256) sf[e] = features[b * EE + e];
    __syncthreads();
    for (int e = tid; e < EE; e += 256) d_xs[b * KP + 25 + e] = embed[e]; // word0 = row 0
    for (int j = tid; j < HH; j += 256) {
        float s = szb[j];
        const float* w = szW + j * EE;
        #pragma unroll 8
        for (int e = 0; e < EE; e++) s += sf[e] * w[e];
        d_xs[b * KP + 281 + j] = s;
    }
}

// ---------------------------------------------------------------------------
// Gate GEMM (one per LSTM step): gpart[ks][b][n] = sum over K-segment of
// xs[b][k] * Wcat[n][k].   Tile M=64 (all b) x N=64, split-K = 7.
// ---------------------------------------------------------------------------
__global__ __launch_bounds__(256) void k_gates() {
    __shared__ float sa[32][65];
    __shared__ float sb[32][65];
    int tid = threadIdx.x;
    int tn = tid & 31;
    int tm = tid >> 5;           // 0..7, each thread covers 8 b-rows
    int nBase = blockIdx.x * 64;
    int ks = blockIdx.y;
    int k0base = ks * KSEG;

    float acc[8][2];
    #pragma unroll
    for (int i = 0; i < 8; i++) { acc[i][0] = 0.0f; acc[i][1] = 0.0f; }

    for (int c = 0; c < KSEG; c += 32) {
        int k0 = k0base + c;
        #pragma unroll
        for (int l = 0; l < 8; l++) {
            int idx = tid + l * 256;
            int r = idx >> 5, kk = idx & 31;
            sa[kk][r] = d_xs[r * KP + k0 + kk];
            sb[kk][r] = d_Wcat[(nBase + r) * KP + k0 + kk];
        }
        __syncthreads();
        #pragma unroll 8
        for (int kk = 0; kk < 32; kk++) {
            float b0 = sb[kk][tn];
            float b1 = sb[kk][tn + 32];
            #pragma unroll
            for (int i = 0; i < 8; i++) {
                float a = sa[kk][tm * 8 + i];
                acc[i][0] += a * b0;
                acc[i][1] += a * b1;
            }
        }
        __syncthreads();
    }
    float* gp = d_gpart + ks * (BB * NR);
    #pragma unroll
    for (int i = 0; i < 8; i++) {
        int b = tm * 8 + i;
        gp[b * NR + nBase + tn]      = acc[i][0];
        gp[b * NR + nBase + tn + 32] = acc[i][1];
    }
}

// ---------------------------------------------------------------------------
// Cell update + Kronecker feature + next-word embed. One block per batch row.
// Step t (0..22). Writes wordOut[t+1].
// ---------------------------------------------------------------------------
__global__ __launch_bounds__(256) void k_cellft(int t, const int* __restrict__ captions,
                                                const float* __restrict__ embed,
                                                const float* __restrict__ wuW,
                                                const float* __restrict__ wub) {
    int b = blockIdx.x;
    int tid = threadIdx.x;
    __shared__ float shS[HH];
    __shared__ float shU[DDIM];
    __shared__ float sut[HH];

    for (int j = tid; j < 650; j += 256) {
        int gi, st, coff, hoff;
        if (j < 625) { gi = j;                st = 625; coff = 281 + j;        hoff = 906 + j; }
        else         { gi = 2500 + (j - 625); st = 25;  coff = (j - 625);      hoff = 1531 + (j - 625); }
        float si = d_bias[gi], sf = d_bias[gi + st], sg = d_bias[gi + 2 * st], so = d_bias[gi + 3 * st];
        #pragma unroll
        for (int s = 0; s < KSPLIT; s++) {
            const float* gp = d_gpart + s * (BB * NR) + b * NR;
            si += gp[gi]; sf += gp[gi + st]; sg += gp[gi + 2 * st]; so += gp[gi + 3 * st];
        }
        float c_old = d_xs[b * KP + coff];
        float c = sigm(sf) * c_old + sigm(si) * tanhf(sg);
        float h = sigm(so) * tanhf(c);
        d_xs[b * KP + coff] = c;
        d_xs[b * KP + hoff] = h;
        if (j < 625) shS[j] = h; else shU[j - 625] = h;
    }
    __syncthreads();
    // ut = hU @ wuW.T + wub   (625 outputs, K=25)
    for (int j = tid; j < HH; j += 256) {
        float s = wub[j];
        const float* w = wuW + j * DDIM;
        #pragma unroll
        for (int e = 0; e < DDIM; e++) s += shU[e] * w[e];
        sut[j] = s;
    }
    __syncthreads();
    // ft[r,c] = sum_m ut[r,m] * hS[m,c]
    for (int j = tid; j < HH; j += 256) {
        int r = j / DDIM, c = j % DDIM;
        float s = 0.0f;
        #pragma unroll
        for (int m = 0; m < DDIM; m++) s += sut[r * DDIM + m] * shS[m * DDIM + c];
        d_wordOut[(t + 1) * (BB * WO_LD) + b * WO_LD + j] = s;
    }
    // next word for step t+1 (steps 1..22 use captions[:, t])
    if (t + 1 <= 22) {
        int w = captions[b * TTOT + (t + 1)];
        for (int e = tid; e < EE; e += 256)
            d_xs[b * KP + 25 + e] = embed[w * EE + e];
    }
}

// ---------------------------------------------------------------------------
// Final FC: out[1536 x 32000] = wordOut[1536 x 640] @ fcWp.T + fcb
// Tile 128x128, 256 threads, 8x8 microtile. Slice 0 rows are zeros -> fcb.
// ---------------------------------------------------------------------------
__global__ __launch_bounds__(256) void k_fc(const float* __restrict__ fcb, float* __restrict__ out) {
    __shared__ __align__(16) float sa[32][132];
    __shared__ __align__(16) float sb[32][132];
    int tid = threadIdx.x;
    int tn = tid & 15;
    int tm = tid >> 4;   // 0..15
    int mBase = blockIdx.y * 128;
    int nBase = blockIdx.x * 128;

    float acc[8][8];
    #pragma unroll
    for (int i = 0; i < 8; i++)
        #pragma unroll
        for (int j = 0; j < 8; j++) acc[i][j] = 0.0f;

    for (int k0 = 0; k0 < WO_LD; k0 += 32) {
        #pragma unroll
        for (int l = 0; l < 16; l++) {
            int idx = tid + l * 256;
            int r = idx >> 5, kk = idx & 31;
            sa[kk][r] = d_wordOut[(mBase + r) * WO_LD + k0 + kk];
            sb[kk][r] = d_fcWp[(nBase + r) * WO_LD + k0 + kk];
        }
        __syncthreads();
        #pragma unroll 8
        for (int kk = 0; kk < 32; kk++) {
            float4 a0 = *(const float4*)&sa[kk][tm * 8];
            float4 a1 = *(const float4*)&sa[kk][tm * 8 + 4];
            float4 b0 = *(const float4*)&sb[kk][tn * 8];
            float4 b1 = *(const float4*)&sb[kk][tn * 8 + 4];
            float av[8] = {a0.x, a0.y, a0.z, a0.w, a1.x, a1.y, a1.z, a1.w};
            float bv[8] = {b0.x, b0.y, b0.z, b0.w, b1.x, b1.y, b1.z, b1.w};
            #pragma unroll
            for (int i = 0; i < 8; i++)
                #pragma unroll
                for (int j = 0; j < 8; j++)
                    acc[i][j] += av[i] * bv[j];
        }
        __syncthreads();
    }
    #pragma unroll
    for (int i = 0; i < 8; i++) {
        int row = mBase + tm * 8 + i;
        float* o = out + (size_t)row * VV + nBase + tn * 8;
        const float* bia = fcb + nBase + tn * 8;
        #pragma unroll
        for (int j = 0; j < 8; j++) o[j] = acc[i][j] + bia[j];
    }
}

// ---------------------------------------------------------------------------
extern "C" void kernel_launch(void* const* d_in, const int* in_sizes, int n_in,
                              void* d_out, int out_size) {
    const float* features = (const float*)d_in[0];
    const int*   captions = (const int*)  d_in[1];
    const float* embed    = (const float*)d_in[2];
    const float* WihS     = (const float*)d_in[3];
    const float* WhhS     = (const float*)d_in[4];
    const float* bihS     = (const float*)d_in[5];
    const float* bhhS     = (const float*)d_in[6];
    const float* WihU     = (const float*)d_in[7];
    const float* WhhU     = (const float*)d_in[8];
    const float* bihU     = (const float*)d_in[9];
    const float* bhhU     = (const float*)d_in[10];
    const float* fcW      = (const float*)d_in[11];
    const float* fcb      = (const float*)d_in[12];
    const float* szW      = (const float*)d_in[13];
    const float* szb      = (const float*)d_in[14];
    const float* wuW      = (const float*)d_in[15];
    const float* wub      = (const float*)d_in[16];
    float* out = (float*)d_out;

    k_prep_wcat<<<NR, 256>>>(WihS, WhhS, bihS, bhhS, WihU, WhhU, bihU, bhhU);
    k_prep_fcw<<<VV, 256>>>(fcW);
    k_init<<<BB, 256>>>(features, szW, szb, embed);
    k_zero_wo<<<(TTOT * BB * WO_LD + 255) / 256, 256>>>();

    for (int t = 0; t < 23; t++) {
        k_gates<<<dim3(41, KSPLIT), 256>>>();
        k_cellft<<<BB, 256>>>(t, captions, embed, wuW, wub);
    }

    k_fc<<<dim3(250, 12), 256>>>(fcb, out);
}

// round 6
// speedup vs baseline: 1.9162x; 1.9162x over previous
#include <cuda_runtime.h>
#include <cuda_bf16.h>
#include <math.h>
#include <stdint.h>

// Problem constants
#define VV   32000
#define EE   256
#define DDIM 25
#define BB   64
#define TTOT 24
#define HH   625      // D*D
#define KP   1568     // padded K for gate GEMM (49*32)
#define NR   2624     // padded gate rows (41*64); real gates = 2600
#define KSPLIT 7
#define KSEG   224
#define WO_LD  640    // padded H for FC GEMM (10 chunks of 64)

// Scratch (device globals; no runtime allocation)
__device__ float d_Wcat[NR * KP];
__device__ float d_bias[NR];
__device__ float d_xs[BB * KP];
__device__ float d_gpart[KSPLIT * BB * NR];
__device__ float d_wordOut[TTOT * BB * WO_LD];
// bf16 hi/lo decompositions for tensor-core FC
__device__ __nv_bfloat16 d_fcHi[VV * WO_LD];
__device__ __nv_bfloat16 d_fcLo[VV * WO_LD];
__device__ __nv_bfloat16 d_woHi[TTOT * BB * WO_LD];
__device__ __nv_bfloat16 d_woLo[TTOT * BB * WO_LD];

__device__ __forceinline__ float sigm(float x) { return 1.0f / (1.0f + expf(-x)); }

__device__ __forceinline__ uint32_t smem_u32(const void* p) {
    uint32_t a;
    asm("{ .reg .u64 t; cvta.to.shared.u64 t, %1; cvt.u32.u64 %0, t; }" : "=r"(a) : "l"(p));
    return a;
}
#define LDSM4(r0, r1, r2, r3, a) \
    asm volatile("ldmatrix.sync.aligned.m8n8.x4.shared.b16 {%0,%1,%2,%3}, [%4];" \
                 : "=r"(r0), "=r"(r1), "=r"(r2), "=r"(r3) : "r"(a))

__device__ __forceinline__ void mma_bf16(float* c, const uint32_t* a, const uint32_t* b) {
    asm volatile("mma.sync.aligned.m16n8k16.row.col.f32.bf16.bf16.f32 "
                 "{%0,%1,%2,%3}, {%4,%5,%6,%7}, {%8,%9}, {%0,%1,%2,%3};"
                 : "+f"(c[0]), "+f"(c[1]), "+f"(c[2]), "+f"(c[3])
                 : "r"(a[0]), "r"(a[1]), "r"(a[2]), "r"(a[3]), "r"(b[0]), "r"(b[1]));
}

// ============================ prep kernels ============================
__global__ void k_prep_wcat(const float* __restrict__ WihS, const float* __restrict__ WhhS,
                            const float* __restrict__ bihS, const float* __restrict__ bhhS,
                            const float* __restrict__ WihU, const float* __restrict__ WhhU,
                            const float* __restrict__ bihU, const float* __restrict__ bhhU) {
    int r = blockIdx.x;
    int tid = threadIdx.x;
    for (int c = tid; c < KP; c += 256) {
        float v = 0.0f;
        if (r < 2500) {
            if (c < 906)        v = WihS[r * 906 + c];
            else if (c < 1531)  v = WhhS[r * 625 + (c - 906)];
        } else if (r < 2600) {
            int r2 = r - 2500;
            if (c < 906)                    v = WihU[r2 * 906 + c];
            else if (c >= 1531 && c < 1556) v = WhhU[r2 * 25 + (c - 1531)];
        }
        d_Wcat[r * KP + c] = v;
    }
    if (tid == 0) {
        float bv = 0.0f;
        if (r < 2500)       bv = bihS[r] + bhhS[r];
        else if (r < 2600)  bv = bihU[r - 2500] + bhhU[r - 2500];
        d_bias[r] = bv;
    }
}

// fcW [32000 x 625] -> bf16 hi/lo [32000 x 640] (pad zeros)
__global__ void k_prep_fcw(const float* __restrict__ fcW) {
    int n = blockIdx.x;
    int tid = threadIdx.x;
    for (int k = tid; k < WO_LD; k += 256) {
        float x = (k < 625) ? fcW[n * 625 + k] : 0.0f;
        __nv_bfloat16 h = __float2bfloat16(x);
        __nv_bfloat16 l = __float2bfloat16(x - __bfloat162float(h));
        d_fcHi[n * WO_LD + k] = h;
        d_fcLo[n * WO_LD + k] = l;
    }
}

__global__ void k_zero_wo() {
    int i = blockIdx.x * 256 + threadIdx.x;
    if (i < TTOT * BB * WO_LD) d_wordOut[i] = 0.0f;
}

__global__ void k_init(const float* __restrict__ features, const float* __restrict__ szW,
                       const float* __restrict__ szb, const float* __restrict__ embed) {
    int b = blockIdx.x;
    int tid = threadIdx.x;
    __shared__ float sf[EE];
    for (int k = tid; k < KP; k += 256) d_xs[b * KP + k] = 0.0f;
    for (int e = tid; e < EE; e += 256) sf[e] = features[b * EE + e];
    __syncthreads();
    for (int e = tid; e < EE; e += 256) d_xs[b * KP + 25 + e] = embed[e];
    for (int j = tid; j < HH; j += 256) {
        float s = szb[j];
        const float* w = szW + j * EE;
        #pragma unroll 8
        for (int e = 0; e < EE; e++) s += sf[e] * w[e];
        d_xs[b * KP + 281 + j] = s;
    }
}

// ============================ LSTM step kernels ============================
__global__ __launch_bounds__(256) void k_gates() {
    __shared__ float sa[32][65];
    __shared__ float sb[32][65];
    int tid = threadIdx.x;
    int tn = tid & 31;
    int tm = tid >> 5;
    int nBase = blockIdx.x * 64;
    int ks = blockIdx.y;
    int k0base = ks * KSEG;

    float acc[8][2];
    #pragma unroll
    for (int i = 0; i < 8; i++) { acc[i][0] = 0.0f; acc[i][1] = 0.0f; }

    for (int c = 0; c < KSEG; c += 32) {
        int k0 = k0base + c;
        #pragma unroll
        for (int l = 0; l < 8; l++) {
            int idx = tid + l * 256;
            int r = idx >> 5, kk = idx & 31;
            sa[kk][r] = d_xs[r * KP + k0 + kk];
            sb[kk][r] = d_Wcat[(nBase + r) * KP + k0 + kk];
        }
        __syncthreads();
        #pragma unroll 8
        for (int kk = 0; kk < 32; kk++) {
            float b0 = sb[kk][tn];
            float b1 = sb[kk][tn + 32];
            #pragma unroll
            for (int i = 0; i < 8; i++) {
                float a = sa[kk][tm * 8 + i];
                acc[i][0] += a * b0;
                acc[i][1] += a * b1;
            }
        }
        __syncthreads();
    }
    float* gp = d_gpart + ks * (BB * NR);
    #pragma unroll
    for (int i = 0; i < 8; i++) {
        int b = tm * 8 + i;
        gp[b * NR + nBase + tn]      = acc[i][0];
        gp[b * NR + nBase + tn + 32] = acc[i][1];
    }
}

__global__ __launch_bounds__(256) void k_cellft(int t, const int* __restrict__ captions,
                                                const float* __restrict__ embed,
                                                const float* __restrict__ wuW,
                                                const float* __restrict__ wub) {
    int b = blockIdx.x;
    int tid = threadIdx.x;
    __shared__ float shS[HH];
    __shared__ float shU[DDIM];
    __shared__ float sut[HH];

    for (int j = tid; j < 650; j += 256) {
        int gi, st, coff, hoff;
        if (j < 625) { gi = j;                st = 625; coff = 281 + j;   hoff = 906 + j; }
        else         { gi = 2500 + (j - 625); st = 25;  coff = (j - 625); hoff = 1531 + (j - 625); }
        float si = d_bias[gi], sf = d_bias[gi + st], sg = d_bias[gi + 2 * st], so = d_bias[gi + 3 * st];
        #pragma unroll
        for (int s = 0; s < KSPLIT; s++) {
            const float* gp = d_gpart + s * (BB * NR) + b * NR;
            si += gp[gi]; sf += gp[gi + st]; sg += gp[gi + 2 * st]; so += gp[gi + 3 * st];
        }
        float c_old = d_xs[b * KP + coff];
        float c = sigm(sf) * c_old + sigm(si) * tanhf(sg);
        float h = sigm(so) * tanhf(c);
        d_xs[b * KP + coff] = c;
        d_xs[b * KP + hoff] = h;
        if (j < 625) shS[j] = h; else shU[j - 625] = h;
    }
    __syncthreads();
    for (int j = tid; j < HH; j += 256) {
        float s = wub[j];
        const float* w = wuW + j * DDIM;
        #pragma unroll
        for (int e = 0; e < DDIM; e++) s += shU[e] * w[e];
        sut[j] = s;
    }
    __syncthreads();
    for (int j = tid; j < HH; j += 256) {
        int r = j / DDIM, c = j % DDIM;
        float s = 0.0f;
        #pragma unroll
        for (int m = 0; m < DDIM; m++) s += sut[r * DDIM + m] * shS[m * DDIM + c];
        d_wordOut[(t + 1) * (BB * WO_LD) + b * WO_LD + j] = s;
    }
    if (t + 1 <= 22) {
        int w = captions[b * TTOT + (t + 1)];
        for (int e = tid; e < EE; e += 256)
            d_xs[b * KP + 25 + e] = embed[w * EE + e];
    }
}

// Convert fp32 wordOut -> bf16 hi/lo
__global__ void k_conv_wo() {
    int i = blockIdx.x * 256 + threadIdx.x;
    if (i < TTOT * BB * WO_LD) {
        float x = d_wordOut[i];
        __nv_bfloat16 h = __float2bfloat16(x);
        __nv_bfloat16 l = __float2bfloat16(x - __bfloat162float(h));
        d_woHi[i] = h;
        d_woLo[i] = l;
    }
}

// ============================ mma.sync FC GEMM ============================
// out[1536 x 32000] = wordOut @ fcW.T + fcb, bf16x3 via HMMA.16816.
// CTA 128(M) x 128(N), K = 640 in 10 chunks of 64. 8 warps: 2(M) x 4(N),
// warp tile 64 x 32 = 4x4 m16n8k16 tiles, 3 terms (AhBh, AhBl, AlBh).
#define CH_K   64
#define NCHUNK 10
#define ALD    72                      // padded row stride in bf16 (144 B)
#define TILEE  (128 * ALD)             // elements per smem tile
#define FC_SMEM (4 * TILEE * 2)        // 73728 bytes

__global__ __launch_bounds__(256) void k_fc_mma(const float* __restrict__ fcb, float* __restrict__ out) {
    extern __shared__ __nv_bfloat16 sm[];
    __nv_bfloat16* sAh = sm;
    __nv_bfloat16* sAl = sm + TILEE;
    __nv_bfloat16* sBh = sm + 2 * TILEE;
    __nv_bfloat16* sBl = sm + 3 * TILEE;

    int tid = threadIdx.x;
    int wid = tid >> 5;
    int lane = tid & 31;
    int wm = wid & 1;          // 0..1 (M)
    int wn = wid >> 1;         // 0..3 (N)
    int mBase = blockIdx.x * 128;   // 12 (fast dim -> B tile reuse in L2)
    int nBase = blockIdx.y * 128;   // 250

    float acc[4][4][4];
    #pragma unroll
    for (int i = 0; i < 4; i++)
        #pragma unroll
        for (int j = 0; j < 4; j++)
            #pragma unroll
            for (int q = 0; q < 4; q++) acc[i][j][q] = 0.0f;

    uint32_t smb = smem_u32(sm);
    // ldmatrix source addresses (per-lane, fixed row/col pattern)
    int aRow = (lane & 15), aKoff = (lane >> 4) * 8;
    int bRow = ((lane >> 4) * 8) + (lane & 7), bKoff = ((lane >> 3) & 1) * 8;

    for (int c = 0; c < NCHUNK; c++) {
        // Load 4 tiles (Ah, Al, Bh, Bl): 128 rows x 64 bf16 each, uint2 chunks
        #pragma unroll
        for (int tsel = 0; tsel < 4; tsel++) {
            const __nv_bfloat16* src =
                (tsel == 0) ? d_woHi : (tsel == 1) ? d_woLo : (tsel == 2) ? d_fcHi : d_fcLo;
            int rowBase = (tsel < 2) ? mBase : nBase;
            __nv_bfloat16* dst = sm + tsel * TILEE;
            #pragma unroll
            for (int l = 0; l < 8; l++) {
                int idx = tid + l * 256;
                int r = idx >> 4, q = idx & 15;
                uint2 v = *(const uint2*)(src + (size_t)(rowBase + r) * WO_LD + c * CH_K + q * 4);
                *(uint2*)(dst + r * ALD + q * 4) = v;
            }
        }
        __syncthreads();

        #pragma unroll
        for (int kk = 0; kk < 4; kk++) {
            uint32_t ah[4][4], al[4][4], bh[4][2], bl[4][2];
            #pragma unroll
            for (int mi = 0; mi < 4; mi++) {
                uint32_t off = (uint32_t)((wm * 64 + mi * 16 + aRow) * ALD + kk * 16 + aKoff) * 2;
                LDSM4(ah[mi][0], ah[mi][1], ah[mi][2], ah[mi][3], smb + off);
                LDSM4(al[mi][0], al[mi][1], al[mi][2], al[mi][3], smb + (uint32_t)(TILEE * 2) + off);
            }
            #pragma unroll
            for (int j = 0; j < 2; j++) {
                uint32_t off = (uint32_t)((wn * 32 + j * 16 + bRow) * ALD + kk * 16 + bKoff) * 2;
                uint32_t r0, r1, r2, r3;
                LDSM4(r0, r1, r2, r3, smb + (uint32_t)(2 * TILEE * 2) + off);
                bh[2 * j][0] = r0; bh[2 * j][1] = r1; bh[2 * j + 1][0] = r2; bh[2 * j + 1][1] = r3;
                LDSM4(r0, r1, r2, r3, smb + (uint32_t)(3 * TILEE * 2) + off);
                bl[2 * j][0] = r0; bl[2 * j][1] = r1; bl[2 * j + 1][0] = r2; bl[2 * j + 1][1] = r3;
            }
            #pragma unroll
            for (int mi = 0; mi < 4; mi++)
                #pragma unroll
                for (int ni = 0; ni < 4; ni++) {
                    mma_bf16(acc[mi][ni], ah[mi], bh[ni]);
                    mma_bf16(acc[mi][ni], ah[mi], bl[ni]);
                    mma_bf16(acc[mi][ni], al[mi], bh[ni]);
                }
        }
        __syncthreads();
    }

    // Epilogue: direct coalesced-enough float2 stores (+bias)
    int g = lane >> 2, tig = lane & 3;
    #pragma unroll
    for (int ni = 0; ni < 4; ni++) {
        int col = nBase + wn * 32 + ni * 8 + 2 * tig;
        float b0 = fcb[col], b1 = fcb[col + 1];
        #pragma unroll
        for (int mi = 0; mi < 4; mi++) {
            int row0 = mBase + wm * 64 + mi * 16 + g;
            float2 v0 = { acc[mi][ni][0] + b0, acc[mi][ni][1] + b1 };
            float2 v1 = { acc[mi][ni][2] + b0, acc[mi][ni][3] + b1 };
            *(float2*)&out[(size_t)row0 * VV + col] = v0;
            *(float2*)&out[(size_t)(row0 + 8) * VV + col] = v1;
        }
    }
}

// ---------------------------------------------------------------------------
extern "C" void kernel_launch(void* const* d_in, const int* in_sizes, int n_in,
                              void* d_out, int out_size) {
    const float* features = (const float*)d_in[0];
    const int*   captions = (const int*)  d_in[1];
    const float* embed    = (const float*)d_in[2];
    const float* WihS     = (const float*)d_in[3];
    const float* WhhS     = (const float*)d_in[4];
    const float* bihS     = (const float*)d_in[5];
    const float* bhhS     = (const float*)d_in[6];
    const float* WihU     = (const float*)d_in[7];
    const float* WhhU     = (const float*)d_in[8];
    const float* bihU     = (const float*)d_in[9];
    const float* bhhU     = (const float*)d_in[10];
    const float* fcW      = (const float*)d_in[11];
    const float* fcb      = (const float*)d_in[12];
    const float* szW      = (const float*)d_in[13];
    const float* szb      = (const float*)d_in[14];
    const float* wuW      = (const float*)d_in[15];
    const float* wub      = (const float*)d_in[16];
    float* out = (float*)d_out;

    cudaFuncSetAttribute(k_fc_mma, cudaFuncAttributeMaxDynamicSharedMemorySize, FC_SMEM);

    k_prep_wcat<<<NR, 256>>>(WihS, WhhS, bihS, bhhS, WihU, WhhU, bihU, bhhU);
    k_prep_fcw<<<VV, 256>>>(fcW);
    k_init<<<BB, 256>>>(features, szW, szb, embed);
    k_zero_wo<<<(TTOT * BB * WO_LD + 255) / 256, 256>>>();

    for (int t = 0; t < 23; t++) {
        k_gates<<<dim3(41, KSPLIT), 256>>>();
        k_cellft<<<BB, 256>>>(t, captions, embed, wuW, wub);
    }

    k_conv_wo<<<(TTOT * BB * WO_LD + 255) / 256, 256>>>();
    k_fc_mma<<<dim3(12, 250), 256, FC_SMEM>>>(fcb, out);
}

// round 7
// speedup vs baseline: 2.2477x; 1.1730x over previous
#include <cuda_runtime.h>
#include <cuda_bf16.h>
#include <math.h>
#include <stdint.h>

// Problem constants
#define VV   32000
#define EE   256
#define DDIM 25
#define BB   64
#define TTOT 24
#define HH   625      // D*D
// xs layout: [0,25) cU | [25,281) word | [281,906) cS | [906,1531) hS | [1531,1556) hU | pad -> 1600
#define KP2  1600     // padded K for gate mma (25 chunks of 64)
#define NR   2624     // padded gate rows (41*64); real gates = 2600
#define GSPLIT 5
#define GSEG   320    // KP2 / GSPLIT = 5 chunks of 64
#define WO_LD  640    // padded H for FC GEMM (10 chunks of 64)

// Scratch (device globals; no runtime allocation)
__device__ float d_bias[NR];
__device__ float d_xs[BB * KP2];
__device__ __nv_bfloat16 d_xsHi[BB * KP2];
__device__ __nv_bfloat16 d_xsLo[BB * KP2];
__device__ __nv_bfloat16 d_WcatHi[NR * KP2];
__device__ __nv_bfloat16 d_WcatLo[NR * KP2];
__device__ float d_gpart[GSPLIT * BB * NR];
__device__ float d_wordOut[TTOT * BB * WO_LD];
__device__ __nv_bfloat16 d_fcHi[VV * WO_LD];
__device__ __nv_bfloat16 d_fcLo[VV * WO_LD];
__device__ __nv_bfloat16 d_woHi[TTOT * BB * WO_LD];
__device__ __nv_bfloat16 d_woLo[TTOT * BB * WO_LD];

__device__ __forceinline__ float sigm(float x) { return 1.0f / (1.0f + expf(-x)); }

__device__ __forceinline__ void set_xs(int b, int k, float v) {
    d_xs[b * KP2 + k] = v;
    __nv_bfloat16 h = __float2bfloat16(v);
    d_xsHi[b * KP2 + k] = h;
    d_xsLo[b * KP2 + k] = __float2bfloat16(v - __bfloat162float(h));
}

__device__ __forceinline__ uint32_t smem_u32(const void* p) {
    uint32_t a;
    asm("{ .reg .u64 t; cvta.to.shared.u64 t, %1; cvt.u32.u64 %0, t; }" : "=r"(a) : "l"(p));
    return a;
}
#define LDSM4(r0, r1, r2, r3, a) \
    asm volatile("ldmatrix.sync.aligned.m8n8.x4.shared.b16 {%0,%1,%2,%3}, [%4];" \
                 : "=r"(r0), "=r"(r1), "=r"(r2), "=r"(r3) : "r"(a))

__device__ __forceinline__ void mma_bf16(float* c, const uint32_t* a, const uint32_t* b) {
    asm volatile("mma.sync.aligned.m16n8k16.row.col.f32.bf16.bf16.f32 "
                 "{%0,%1,%2,%3}, {%4,%5,%6,%7}, {%8,%9}, {%0,%1,%2,%3};"
                 : "+f"(c[0]), "+f"(c[1]), "+f"(c[2]), "+f"(c[3])
                 : "r"(a[0]), "r"(a[1]), "r"(a[2]), "r"(a[3]), "r"(b[0]), "r"(b[1]));
}

// ============================ prep kernels ============================
// Build concatenated gate weights directly as bf16 hi/lo + summed bias.
__global__ void k_prep_wcat(const float* __restrict__ WihS, const float* __restrict__ WhhS,
                            const float* __restrict__ bihS, const float* __restrict__ bhhS,
                            const float* __restrict__ WihU, const float* __restrict__ WhhU,
                            const float* __restrict__ bihU, const float* __restrict__ bhhU) {
    int r = blockIdx.x;
    int tid = threadIdx.x;
    for (int c = tid; c < KP2; c += 256) {
        float v = 0.0f;
        if (r < 2500) {
            if (c < 906)        v = WihS[r * 906 + c];
            else if (c < 1531)  v = WhhS[r * 625 + (c - 906)];
        } else if (r < 2600) {
            int r2 = r - 2500;
            if (c < 906)                    v = WihU[r2 * 906 + c];
            else if (c >= 1531 && c < 1556) v = WhhU[r2 * 25 + (c - 1531)];
        }
        __nv_bfloat16 h = __float2bfloat16(v);
        d_WcatHi[r * KP2 + c] = h;
        d_WcatLo[r * KP2 + c] = __float2bfloat16(v - __bfloat162float(h));
    }
    if (tid == 0) {
        float bv = 0.0f;
        if (r < 2500)       bv = bihS[r] + bhhS[r];
        else if (r < 2600)  bv = bihU[r - 2500] + bhhU[r - 2500];
        d_bias[r] = bv;
    }
}

// fcW [32000 x 625] -> bf16 hi/lo [32000 x 640] (pad zeros)
__global__ void k_prep_fcw(const float* __restrict__ fcW) {
    int n = blockIdx.x;
    int tid = threadIdx.x;
    for (int k = tid; k < WO_LD; k += 256) {
        float x = (k < 625) ? fcW[n * 625 + k] : 0.0f;
        __nv_bfloat16 h = __float2bfloat16(x);
        __nv_bfloat16 l = __float2bfloat16(x - __bfloat162float(h));
        d_fcHi[n * WO_LD + k] = h;
        d_fcLo[n * WO_LD + k] = l;
    }
}

__global__ void k_zero_wo() {
    int i = blockIdx.x * 256 + threadIdx.x;
    if (i < TTOT * BB * WO_LD) d_wordOut[i] = 0.0f;
}

__global__ void k_init(const float* __restrict__ features, const float* __restrict__ szW,
                       const float* __restrict__ szb, const float* __restrict__ embed) {
    int b = blockIdx.x;
    int tid = threadIdx.x;
    __shared__ float sf[EE];
    for (int k = tid; k < KP2; k += 256) {
        d_xs[b * KP2 + k] = 0.0f;
        d_xsHi[b * KP2 + k] = __float2bfloat16(0.0f);
        d_xsLo[b * KP2 + k] = __float2bfloat16(0.0f);
    }
    for (int e = tid; e < EE; e += 256) sf[e] = features[b * EE + e];
    __syncthreads();
    for (int e = tid; e < EE; e += 256) set_xs(b, 25 + e, embed[e]);
    for (int j = tid; j < HH; j += 256) {
        float s = szb[j];
        const float* w = szW + j * EE;
        #pragma unroll 8
        for (int e = 0; e < EE; e++) s += sf[e] * w[e];
        set_xs(b, 281 + j, s);
    }
}

// ============================ gate GEMM via mma.sync ============================
// gpart[ks][b][n] = sum over K-segment of xs[b][k] * Wcat[n][k], bf16x3.
// CTA: 64(M=batch) x 64(N), split-K = 5 segments of 320 (5 chunks of 64).
// 4 warps, warp tile 64x16.
#define GALD   72
#define GTILEE (64 * GALD)

__global__ __launch_bounds__(128) void k_gates_mma() {
    __shared__ __nv_bfloat16 sm[4 * GTILEE];   // Ah, Al, Bh, Bl = 36864 B
    int tid = threadIdx.x;
    int wid = tid >> 5;        // 0..3 -> N sub-tile
    int lane = tid & 31;
    int nBase = blockIdx.x * 64;
    int ks = blockIdx.y;
    int k0 = ks * GSEG;

    float acc[4][2][4];
    #pragma unroll
    for (int i = 0; i < 4; i++)
        #pragma unroll
        for (int j = 0; j < 2; j++)
            #pragma unroll
            for (int q = 0; q < 4; q++) acc[i][j][q] = 0.0f;

    uint32_t smb = smem_u32(sm);
    int aRow = (lane & 15), aKoff = (lane >> 4) * 8;
    int bRow = ((lane >> 4) * 8) + (lane & 7), bKoff = ((lane >> 3) & 1) * 8;

    for (int c = 0; c < 5; c++) {
        #pragma unroll
        for (int tsel = 0; tsel < 4; tsel++) {
            const __nv_bfloat16* src =
                (tsel == 0) ? d_xsHi : (tsel == 1) ? d_xsLo : (tsel == 2) ? d_WcatHi : d_WcatLo;
            int rowBase = (tsel < 2) ? 0 : nBase;
            __nv_bfloat16* dst = sm + tsel * GTILEE;
            #pragma unroll
            for (int l = 0; l < 8; l++) {
                int idx = tid + l * 128;        // 1024 uint2 per tile
                int r = idx >> 4, q = idx & 15;
                uint2 v = *(const uint2*)(src + (size_t)(rowBase + r) * KP2 + k0 + c * 64 + q * 4);
                *(uint2*)(dst + r * GALD + q * 4) = v;
            }
        }
        __syncthreads();

        #pragma unroll
        for (int kk = 0; kk < 4; kk++) {
            uint32_t ah[4][4], al[4][4], bh[2][2], bl[2][2];
            #pragma unroll
            for (int mi = 0; mi < 4; mi++) {
                uint32_t off = (uint32_t)((mi * 16 + aRow) * GALD + kk * 16 + aKoff) * 2;
                LDSM4(ah[mi][0], ah[mi][1], ah[mi][2], ah[mi][3], smb + off);
                LDSM4(al[mi][0], al[mi][1], al[mi][2], al[mi][3], smb + (uint32_t)(GTILEE * 2) + off);
            }
            {
                uint32_t off = (uint32_t)((wid * 16 + bRow) * GALD + kk * 16 + bKoff) * 2;
                uint32_t r0, r1, r2, r3;
                LDSM4(r0, r1, r2, r3, smb + (uint32_t)(2 * GTILEE * 2) + off);
                bh[0][0] = r0; bh[0][1] = r1; bh[1][0] = r2; bh[1][1] = r3;
                LDSM4(r0, r1, r2, r3, smb + (uint32_t)(3 * GTILEE * 2) + off);
                bl[0][0] = r0; bl[0][1] = r1; bl[1][0] = r2; bl[1][1] = r3;
            }
            #pragma unroll
            for (int mi = 0; mi < 4; mi++)
                #pragma unroll
                for (int ni = 0; ni < 2; ni++) {
                    mma_bf16(acc[mi][ni], ah[mi], bh[ni]);
                    mma_bf16(acc[mi][ni], ah[mi], bl[ni]);
                    mma_bf16(acc[mi][ni], al[mi], bh[ni]);
                }
        }
        __syncthreads();
    }

    float* gp = d_gpart + ks * (BB * NR);
    int g = lane >> 2, tig = lane & 3;
    #pragma unroll
    for (int ni = 0; ni < 2; ni++) {
        int col = nBase + wid * 16 + ni * 8 + 2 * tig;
        #pragma unroll
        for (int mi = 0; mi < 4; mi++) {
            int row0 = mi * 16 + g;
            float2 v0 = { acc[mi][ni][0], acc[mi][ni][1] };
            float2 v1 = { acc[mi][ni][2], acc[mi][ni][3] };
            *(float2*)&gp[(size_t)row0 * NR + col] = v0;
            *(float2*)&gp[(size_t)(row0 + 8) * NR + col] = v1;
        }
    }
}

// ============================ cell update ============================
__global__ __launch_bounds__(256) void k_cellft(int t, const int* __restrict__ captions,
                                                const float* __restrict__ embed,
                                                const float* __restrict__ wuW,
                                                const float* __restrict__ wub) {
    int b = blockIdx.x;
    int tid = threadIdx.x;
    __shared__ float shS[HH];
    __shared__ float shU[DDIM];
    __shared__ float sut[HH];

    for (int j = tid; j < 650; j += 256) {
        int gi, st, coff, hoff;
        if (j < 625) { gi = j;                st = 625; coff = 281 + j;   hoff = 906 + j; }
        else         { gi = 2500 + (j - 625); st = 25;  coff = (j - 625); hoff = 1531 + (j - 625); }
        float si = d_bias[gi], sf = d_bias[gi + st], sg = d_bias[gi + 2 * st], so = d_bias[gi + 3 * st];
        #pragma unroll
        for (int s = 0; s < GSPLIT; s++) {
            const float* gp = d_gpart + s * (BB * NR) + b * NR;
            si += gp[gi]; sf += gp[gi + st]; sg += gp[gi + 2 * st]; so += gp[gi + 3 * st];
        }
        float c_old = d_xs[b * KP2 + coff];
        float c = sigm(sf) * c_old + sigm(si) * tanhf(sg);
        float h = sigm(so) * tanhf(c);
        set_xs(b, coff, c);
        set_xs(b, hoff, h);
        if (j < 625) shS[j] = h; else shU[j - 625] = h;
    }
    __syncthreads();
    for (int j = tid; j < HH; j += 256) {
        float s = wub[j];
        const float* w = wuW + j * DDIM;
        #pragma unroll
        for (int e = 0; e < DDIM; e++) s += shU[e] * w[e];
        sut[j] = s;
    }
    __syncthreads();
    for (int j = tid; j < HH; j += 256) {
        int r = j / DDIM, c = j % DDIM;
        float s = 0.0f;
        #pragma unroll
        for (int m = 0; m < DDIM; m++) s += sut[r * DDIM + m] * shS[m * DDIM + c];
        d_wordOut[(t + 1) * (BB * WO_LD) + b * WO_LD + j] = s;
    }
    if (t + 1 <= 22) {
        int w = captions[b * TTOT + (t + 1)];
        for (int e = tid; e < EE; e += 256)
            set_xs(b, 25 + e, embed[w * EE + e]);
    }
}

// Convert fp32 wordOut -> bf16 hi/lo
__global__ void k_conv_wo() {
    int i = blockIdx.x * 256 + threadIdx.x;
    if (i < TTOT * BB * WO_LD) {
        float x = d_wordOut[i];
        __nv_bfloat16 h = __float2bfloat16(x);
        __nv_bfloat16 l = __float2bfloat16(x - __bfloat162float(h));
        d_woHi[i] = h;
        d_woLo[i] = l;
    }
}

// ============================ mma.sync FC GEMM ============================
// out[1536 x 32000] = wordOut @ fcW.T + fcb, bf16x3 via HMMA.16816.
#define CH_K   64
#define NCHUNK 10
#define ALD    72
#define TILEE  (128 * ALD)
#define FC_SMEM (4 * TILEE * 2)        // 73728 bytes

__global__ __launch_bounds__(256) void k_fc_mma(const float* __restrict__ fcb, float* __restrict__ out) {
    extern __shared__ __nv_bfloat16 sm[];

    int tid = threadIdx.x;
    int wid = tid >> 5;
    int lane = tid & 31;
    int wm = wid & 1;
    int wn = wid >> 1;
    int mBase = blockIdx.x * 128;   // 12 (fast dim -> B tile reuse in L2)
    int nBase = blockIdx.y * 128;   // 250

    float acc[4][4][4];
    #pragma unroll
    for (int i = 0; i < 4; i++)
        #pragma unroll
        for (int j = 0; j < 4; j++)
            #pragma unroll
            for (int q = 0; q < 4; q++) acc[i][j][q] = 0.0f;

    uint32_t smb = smem_u32(sm);
    int aRow = (lane & 15), aKoff = (lane >> 4) * 8;
    int bRow = ((lane >> 4) * 8) + (lane & 7), bKoff = ((lane >> 3) & 1) * 8;

    for (int c = 0; c < NCHUNK; c++) {
        #pragma unroll
        for (int tsel = 0; tsel < 4; tsel++) {
            const __nv_bfloat16* src =
                (tsel == 0) ? d_woHi : (tsel == 1) ? d_woLo : (tsel == 2) ? d_fcHi : d_fcLo;
            int rowBase = (tsel < 2) ? mBase : nBase;
            __nv_bfloat16* dst = sm + tsel * TILEE;
            #pragma unroll
            for (int l = 0; l < 8; l++) {
                int idx = tid + l * 256;
                int r = idx >> 4, q = idx & 15;
                uint2 v = *(const uint2*)(src + (size_t)(rowBase + r) * WO_LD + c * CH_K + q * 4);
                *(uint2*)(dst + r * ALD + q * 4) = v;
            }
        }
        __syncthreads();

        #pragma unroll
        for (int kk = 0; kk < 4; kk++) {
            uint32_t ah[4][4], al[4][4], bh[4][2], bl[4][2];
            #pragma unroll
            for (int mi = 0; mi < 4; mi++) {
                uint32_t off = (uint32_t)((wm * 64 + mi * 16 + aRow) * ALD + kk * 16 + aKoff) * 2;
                LDSM4(ah[mi][0], ah[mi][1], ah[mi][2], ah[mi][3], smb + off);
                LDSM4(al[mi][0], al[mi][1], al[mi][2], al[mi][3], smb + (uint32_t)(TILEE * 2) + off);
            }
            #pragma unroll
            for (int j = 0; j < 2; j++) {
                uint32_t off = (uint32_t)((wn * 32 + j * 16 + bRow) * ALD + kk * 16 + bKoff) * 2;
                uint32_t r0, r1, r2, r3;
                LDSM4(r0, r1, r2, r3, smb + (uint32_t)(2 * TILEE * 2) + off);
                bh[2 * j][0] = r0; bh[2 * j][1] = r1; bh[2 * j + 1][0] = r2; bh[2 * j + 1][1] = r3;
                LDSM4(r0, r1, r2, r3, smb + (uint32_t)(3 * TILEE * 2) + off);
                bl[2 * j][0] = r0; bl[2 * j][1] = r1; bl[2 * j + 1][0] = r2; bl[2 * j + 1][1] = r3;
            }
            #pragma unroll
            for (int mi = 0; mi < 4; mi++)
                #pragma unroll
                for (int ni = 0; ni < 4; ni++) {
                    mma_bf16(acc[mi][ni], ah[mi], bh[ni]);
                    mma_bf16(acc[mi][ni], ah[mi], bl[ni]);
                    mma_bf16(acc[mi][ni], al[mi], bh[ni]);
                }
        }
        __syncthreads();
    }

    int g = lane >> 2, tig = lane & 3;
    #pragma unroll
    for (int ni = 0; ni < 4; ni++) {
        int col = nBase + wn * 32 + ni * 8 + 2 * tig;
        float b0 = fcb[col], b1 = fcb[col + 1];
        #pragma unroll
        for (int mi = 0; mi < 4; mi++) {
            int row0 = mBase + wm * 64 + mi * 16 + g;
            float2 v0 = { acc[mi][ni][0] + b0, acc[mi][ni][1] + b1 };
            float2 v1 = { acc[mi][ni][2] + b0, acc[mi][ni][3] + b1 };
            *(float2*)&out[(size_t)row0 * VV + col] = v0;
            *(float2*)&out[(size_t)(row0 + 8) * VV + col] = v1;
        }
    }
}

// ---------------------------------------------------------------------------
extern "C" void kernel_launch(void* const* d_in, const int* in_sizes, int n_in,
                              void* d_out, int out_size) {
    const float* features = (const float*)d_in[0];
    const int*   captions = (const int*)  d_in[1];
    const float* embed    = (const float*)d_in[2];
    const float* WihS     = (const float*)d_in[3];
    const float* WhhS     = (const float*)d_in[4];
    const float* bihS     = (const float*)d_in[5];
    const float* bhhS     = (const float*)d_in[6];
    const float* WihU     = (const float*)d_in[7];
    const float* WhhU     = (const float*)d_in[8];
    const float* bihU     = (const float*)d_in[9];
    const float* bihU2    = bihU; (void)bihU2;
    const float* bhhU     = (const float*)d_in[10];
    const float* fcW      = (const float*)d_in[11];
    const float* fcb      = (const float*)d_in[12];
    const float* szW      = (const float*)d_in[13];
    const float* szb      = (const float*)d_in[14];
    const float* wuW      = (const float*)d_in[15];
    const float* wub      = (const float*)d_in[16];
    float* out = (float*)d_out;

    cudaFuncSetAttribute(k_fc_mma, cudaFuncAttributeMaxDynamicSharedMemorySize, FC_SMEM);

    k_prep_wcat<<<NR, 256>>>(WihS, WhhS, bihS, bhhS, WihU, WhhU, bihU, bhhU);
    k_prep_fcw<<<VV, 256>>>(fcW);
    k_init<<<BB, 256>>>(features, szW, szb, embed);
    k_zero_wo<<<(TTOT * BB * WO_LD + 255) / 256, 256>>>();

    for (int t = 0; t < 23; t++) {
        k_gates_mma<<<dim3(41, GSPLIT), 128>>>();
        k_cellft<<<BB, 256>>>(t, captions, embed, wuW, wub);
    }

    k_conv_wo<<<(TTOT * BB * WO_LD + 255) / 256, 256>>>();
    k_fc_mma<<<dim3(12, 250), 256, FC_SMEM>>>(fcb, out);
}